// round 12
// baseline (speedup 1.0000x reference)
#include <cuda_runtime.h>
#include <math.h>

#define NN_MAX 50000
#define S_IN 128
#define S_OUT 128
#define K_MERGED 153
#define EPSS 1e-8f
#define NREP 8
#define TILE 64
#define MROW 68   // mT2 row (64 nodes + 4 pad), 272B = 16B-aligned

// dynamic smem layout (float offsets)
#define OFF_MT2   0            // 153*68 = 10404  (aliased by ssm: 64*132 = 8448)
#define OFF_VECS  10404        // 64*52  = 3328
#define OFF_VH    13732        // 64*50  = 3200
#define OFF_GSIG  16932        // 64*16  = 1024
#define OFF_WDOWN 17956        // 256
#define OFF_WUP   18212        // 256
#define SMEM_FLOATS 18468
#define SMEM_BYTES  (SMEM_FLOATS * 4)

// Scratch (static device globals)
__device__ float g_vdf[NN_MAX * 12];
__device__ float g_acc[(size_t)NREP * NN_MAX * 16];
__device__ float g_fold[NN_MAX * 12];
__device__ float g_WsoT[K_MERGED * 128];   // [k][col]
__device__ float g_WgT[128 * 16];          // blocked: [k4][o][kk], k=k4*4+kk
__device__ unsigned int g_ticket;          // dynamic tile counter (zeroed in k_pre)

// ---------------------------------------------------------------------------
// K1: zero accumulators + ticket, compute vdf, transpose W_so and W_g
// ---------------------------------------------------------------------------
__global__ void k_pre(const float* __restrict__ vector,
                      const float* __restrict__ W_df,
                      const float* __restrict__ W_so,
                      const float* __restrict__ W_g,
                      int n_nodes)
{
    int tid = blockIdx.x * blockDim.x + threadIdx.x;

    if (tid == 0) g_ticket = 0u;

    size_t nzero4 = (size_t)NREP * n_nodes * 4;
    if ((size_t)tid < nzero4)
        reinterpret_cast<float4*>(g_acc)[tid] = make_float4(0.f, 0.f, 0.f, 0.f);

    if (tid < K_MERGED * 128) {
        int k = tid >> 7, o = tid & 127;
        g_WsoT[tid] = W_so[o * K_MERGED + k];
    }
    if (tid < 2048) {
        int kk = tid & 3, o = (tid >> 2) & 15, k4 = tid >> 6;
        g_WgT[tid] = W_g[o * 128 + k4 * 4 + kk];
    }

    if (tid >= n_nodes) return;
    int n = tid;

    float v[48];
    const float4* vp = reinterpret_cast<const float4*>(vector + (size_t)n * 48);
#pragma unroll
    for (int q = 0; q < 12; q++) {
        float4 f = vp[q];
        v[q*4+0] = f.x; v[q*4+1] = f.y; v[q*4+2] = f.z; v[q*4+3] = f.w;
    }
#pragma unroll
    for (int j = 0; j < 3; j++) {
        float r0 = 0.f, r1 = 0.f, r2 = 0.f;
#pragma unroll
        for (int i = 0; i < 16; i++) {
            float x = v[i*3 + j];
            r0 += x * __ldg(&W_df[i]);
            r1 += x * __ldg(&W_df[16 + i]);
            r2 += x * __ldg(&W_df[32 + i]);
        }
        g_vdf[(size_t)n*12 + j*3 + 0] = r0;
        g_vdf[(size_t)n*12 + j*3 + 1] = r1;
        g_vdf[(size_t)n*12 + j*3 + 2] = r2;
    }
}

// ---------------------------------------------------------------------------
// K2: per-edge rotation + replicated scatter-add (replica = e & 7)
// ---------------------------------------------------------------------------
__global__ void k_edge(const int* __restrict__ ei,
                       const float* __restrict__ frames,
                       int n_edges, int n_nodes)
{
    int e = blockIdx.x * blockDim.x + threadIdx.x;
    if (e >= n_edges) return;

    int row = ei[e];

    const float4* vp = reinterpret_cast<const float4*>(g_vdf + (size_t)row * 12);
    float4 va = vp[0], vb = vp[1], vc = vp[2];
    float v[9] = { va.x, va.y, va.z, va.w, vb.x, vb.y, vb.z, vb.w, vc.x };

    const float* f = frames + (size_t)e * 9;
    float F[9];
#pragma unroll
    for (int i = 0; i < 9; i++) F[i] = __ldg(&f[i]);

    float loc[9];
#pragma unroll
    for (int x = 0; x < 3; x++)
#pragma unroll
        for (int c = 0; c < 3; c++)
            loc[c*3 + x] = F[x*3+0]*v[0+c] + F[x*3+1]*v[3+c] + F[x*3+2]*v[6+c];

    int rep = e & (NREP - 1);
    float* dst = g_acc + ((size_t)rep * n_nodes + row) * 16;
    asm volatile("red.global.add.v4.f32 [%0], {%1,%2,%3,%4};" ::
                 "l"(dst), "f"(loc[0]), "f"(loc[1]), "f"(loc[2]), "f"(loc[3]) : "memory");
    asm volatile("red.global.add.v4.f32 [%0], {%1,%2,%3,%4};" ::
                 "l"(dst+4), "f"(loc[4]), "f"(loc[5]), "f"(loc[6]), "f"(loc[7]) : "memory");
    asm volatile("red.global.add.v2.f32 [%0], {%1,%2};" ::
                 "l"(dst+8), "f"(loc[8]), "f"(1.0f) : "memory");
}

// ---------------------------------------------------------------------------
// K2b: fold replicas -> meaned 9 values per node
// ---------------------------------------------------------------------------
__global__ void k_fold(int n_nodes)
{
    int n = blockIdx.x * blockDim.x + threadIdx.x;
    if (n >= n_nodes) return;

    float sum[9] = {0,0,0,0,0,0,0,0,0};
    float cnt = 0.f;
#pragma unroll
    for (int r = 0; r < NREP; r++) {
        const float* a = g_acc + ((size_t)r * n_nodes + n) * 16;
        float4 p0 = reinterpret_cast<const float4*>(a)[0];
        float4 p1 = reinterpret_cast<const float4*>(a)[1];
        float2 p2 = reinterpret_cast<const float2*>(a)[4];
        sum[0] += p0.x; sum[1] += p0.y; sum[2] += p0.z; sum[3] += p0.w;
        sum[4] += p1.x; sum[5] += p1.y; sum[6] += p1.z; sum[7] += p1.w;
        sum[8] += p2.x; cnt += p2.y;
    }
    float inv = 1.0f / fmaxf(cnt, 1.0f);
    float* o = g_fold + (size_t)n * 12;
#pragma unroll
    for (int c = 0; c < 9; c++) o[c] = sum[c] * inv;
    o[9] = 0.f; o[10] = 0.f; o[11] = 0.f;
}

// ---------------------------------------------------------------------------
// K3: node MLP. 64-node tiles; warp = 64 cols x 16 nodes (2 cols/lane):
// weight LDG.64 amortized over 16 nodes (0.375 wf/node/k).
// ssm aliases mT2 (dead after GEMM); dynamic smem 74KB, 3 CTAs/SM.
// ---------------------------------------------------------------------------
extern __shared__ float smem[];

__global__ __launch_bounds__(256, 3) void k_post(
    const float* __restrict__ scalar, const float* __restrict__ vector,
    const float* __restrict__ W_down, const float* __restrict__ b_so,
    const float* __restrict__ W_up,
    const float* __restrict__ b_g,
    float* __restrict__ out_s, float* __restrict__ out_v, int n_nodes)
{
    const int t = threadIdx.x;
    const int lane = t & 31;
    const int wid = t >> 5;

    // GEMM assignment: 2 cols, 16 nodes
    const int colh = wid & 1;
    const int nd0g = (wid >> 1) * 16;
    const int c0 = colh * 64 + lane * 2;

    const float2 bso2 = *reinterpret_cast<const float2*>(b_so + c0);

    // gates: o = t&15; nodes ndD, ndD+16, ndD+32, ndD+48
    const int go = t & 15;
    const int ndD = t >> 4;
    const float bg = b_g[go];

    float* const mT2   = smem + OFF_MT2;    // [k*MROW + nd]
    float* const ssm   = smem + OFF_MT2;    // alias: [nd*132 + col] after GEMM
    float* const vecs  = smem + OFF_VECS;   // [nd*52 + c]
    float* const vh    = smem + OFF_VH;     // [nd*50 + ...]
    float* const gsig  = smem + OFF_GSIG;   // [nd*16 + o]
    float* const sWdown= smem + OFF_WDOWN;
    float* const sWup  = smem + OFF_WUP;
    __shared__ int s_tile;

    sWdown[t] = W_down[t];
    sWup[t]   = W_up[t];
    __syncthreads();

    const int ntiles = (n_nodes + TILE - 1) / TILE;
    const int acol = t >> 1, ahalf = t & 1;    // phase A mapping

    while (true) {
        if (t == 0) s_tile = (int)atomicAdd(&g_ticket, 1u);
        __syncthreads();
        const int tile = s_tile;
        if (tile >= ntiles) break;
        const int nb = tile * TILE;

        // ===== Phase A: scalar -> mT2 rows, vecs, sh rows =====
#pragma unroll 4
        for (int i = 0; i < 32; i++) {
            int nd = ahalf * 32 + i;
            int node = nb + nd;
            float p = (node < n_nodes) ? scalar[(size_t)node * 128 + acol] : 0.f;
            mT2[acol * MROW + nd] = p;
        }
#pragma unroll
        for (int r = 0; r < 3; r++) {
            int idx = t + 256 * r;
            int nd = idx / 12, q = idx - nd * 12;
            int node = nb + nd;
            float4 f = (node < n_nodes)
                ? reinterpret_cast<const float4*>(vector)[(size_t)node * 12 + q]
                : make_float4(0.f, 0.f, 0.f, 0.f);
            *reinterpret_cast<float4*>(vecs + nd * 52 + q * 4) = f;
        }
        {
            int nd = t & 63, node = nb + nd;
            for (int c = t >> 6; c < 9; c += 4) {
                float v = (node < n_nodes) ? g_fold[(size_t)node * 12 + c] : 0.f;
                mT2[(144 + c) * MROW + nd] = v;
            }
        }
        __syncthreads();

        // ===== Phase B: vh + vnorm rows (nd = t>>2, 4 h's each) =====
        {
            int nd = t >> 2, h4 = (t & 3) * 4;
#pragma unroll
            for (int hh = 0; hh < 4; hh++) {
                int h = h4 + hh;
                float a0 = 0.f, a1 = 0.f, a2 = 0.f;
#pragma unroll
                for (int i = 0; i < 16; i++) {
                    float wd = sWdown[h * 16 + i];
                    a0 += vecs[nd * 52 + i * 3 + 0] * wd;
                    a1 += vecs[nd * 52 + i * 3 + 1] * wd;
                    a2 += vecs[nd * 52 + i * 3 + 2] * wd;
                }
                vh[nd * 50 +  0 + h] = a0;
                vh[nd * 50 + 16 + h] = a1;
                vh[nd * 50 + 32 + h] = a2;
                mT2[(128 + h) * MROW + nd] = sqrtf(a0*a0 + a1*a1 + a2*a2 + EPSS);
            }
        }
        __syncthreads();

        // ===== Phase C: outer-product GEMM (2 cols x 16 nodes per lane) =====
        {
            unsigned long long acc0[8], acc1[8];
#pragma unroll
            for (int j = 0; j < 8; j++) { acc0[j] = 0ULL; acc1[j] = 0ULL; }

            const float* wbase = g_WsoT + c0;
            const float* mbase = mT2 + nd0g;
#pragma unroll 3
            for (int k = 0; k < K_MERGED; k++) {
                float2 w = __ldg(reinterpret_cast<const float2*>(wbase + (size_t)k * 128));
                const float* mk = mbase + (size_t)k * MROW;
                ulonglong2 mA = *reinterpret_cast<const ulonglong2*>(mk);
                ulonglong2 mB = *reinterpret_cast<const ulonglong2*>(mk + 4);
                ulonglong2 mC = *reinterpret_cast<const ulonglong2*>(mk + 8);
                ulonglong2 mD = *reinterpret_cast<const ulonglong2*>(mk + 12);
                unsigned long long wd0, wd1;
                asm("mov.b64 %0, {%1, %1};" : "=l"(wd0) : "f"(w.x));
                asm("mov.b64 %0, {%1, %1};" : "=l"(wd1) : "f"(w.y));
                asm("fma.rn.f32x2 %0, %1, %2, %0;" : "+l"(acc0[0]) : "l"(wd0), "l"(mA.x));
                asm("fma.rn.f32x2 %0, %1, %2, %0;" : "+l"(acc0[1]) : "l"(wd0), "l"(mA.y));
                asm("fma.rn.f32x2 %0, %1, %2, %0;" : "+l"(acc0[2]) : "l"(wd0), "l"(mB.x));
                asm("fma.rn.f32x2 %0, %1, %2, %0;" : "+l"(acc0[3]) : "l"(wd0), "l"(mB.y));
                asm("fma.rn.f32x2 %0, %1, %2, %0;" : "+l"(acc0[4]) : "l"(wd0), "l"(mC.x));
                asm("fma.rn.f32x2 %0, %1, %2, %0;" : "+l"(acc0[5]) : "l"(wd0), "l"(mC.y));
                asm("fma.rn.f32x2 %0, %1, %2, %0;" : "+l"(acc0[6]) : "l"(wd0), "l"(mD.x));
                asm("fma.rn.f32x2 %0, %1, %2, %0;" : "+l"(acc0[7]) : "l"(wd0), "l"(mD.y));
                asm("fma.rn.f32x2 %0, %1, %2, %0;" : "+l"(acc1[0]) : "l"(wd1), "l"(mA.x));
                asm("fma.rn.f32x2 %0, %1, %2, %0;" : "+l"(acc1[1]) : "l"(wd1), "l"(mA.y));
                asm("fma.rn.f32x2 %0, %1, %2, %0;" : "+l"(acc1[2]) : "l"(wd1), "l"(mB.x));
                asm("fma.rn.f32x2 %0, %1, %2, %0;" : "+l"(acc1[3]) : "l"(wd1), "l"(mB.y));
                asm("fma.rn.f32x2 %0, %1, %2, %0;" : "+l"(acc1[4]) : "l"(wd1), "l"(mC.x));
                asm("fma.rn.f32x2 %0, %1, %2, %0;" : "+l"(acc1[5]) : "l"(wd1), "l"(mC.y));
                asm("fma.rn.f32x2 %0, %1, %2, %0;" : "+l"(acc1[6]) : "l"(wd1), "l"(mD.x));
                asm("fma.rn.f32x2 %0, %1, %2, %0;" : "+l"(acc1[7]) : "l"(wd1), "l"(mD.y));
            }
            // all GEMM reads of mT2 must finish before ssm (alias) is written
            __syncthreads();
#pragma unroll
            for (int j = 0; j < 8; j++) {
                float lo0, hi0, lo1, hi1;
                asm("mov.b64 {%0, %1}, %2;" : "=f"(lo0), "=f"(hi0) : "l"(acc0[j]));
                asm("mov.b64 {%0, %1}, %2;" : "=f"(lo1), "=f"(hi1) : "l"(acc1[j]));
                float sv00 = lo0 + bso2.x, sv01 = lo1 + bso2.y;
                float sv10 = hi0 + bso2.x, sv11 = hi1 + bso2.y;
                float s00 = sv00 / (1.0f + __expf(-sv00));
                float s01 = sv01 / (1.0f + __expf(-sv01));
                float s10 = sv10 / (1.0f + __expf(-sv10));
                float s11 = sv11 / (1.0f + __expf(-sv11));
                *reinterpret_cast<float2*>(ssm + (nd0g + 2*j    ) * 132 + c0) =
                    make_float2(s00, s01);
                *reinterpret_cast<float2*>(ssm + (nd0g + 2*j + 1) * 132 + c0) =
                    make_float2(s10, s11);
            }
        }
        __syncthreads();

        // ===== Phase D: gates (4 nodes per thread, shared weight loads) =====
        {
            float pA = 0.f, pB = 0.f, pC = 0.f, pD = 0.f;
            const float4* wgt = reinterpret_cast<const float4*>(g_WgT + go * 4);
            const float4* sA4 = reinterpret_cast<const float4*>(ssm + (ndD     ) * 132);
            const float4* sB4 = reinterpret_cast<const float4*>(ssm + (ndD + 16) * 132);
            const float4* sC4 = reinterpret_cast<const float4*>(ssm + (ndD + 32) * 132);
            const float4* sD4 = reinterpret_cast<const float4*>(ssm + (ndD + 48) * 132);
#pragma unroll 8
            for (int k4 = 0; k4 < 32; k4++) {
                float4 w = __ldg(wgt + k4 * 16);
                float4 xa = sA4[k4];
                float4 xb = sB4[k4];
                float4 xc = sC4[k4];
                float4 xd = sD4[k4];
                pA += w.x*xa.x + w.y*xa.y + w.z*xa.z + w.w*xa.w;
                pB += w.x*xb.x + w.y*xb.y + w.z*xb.z + w.w*xb.w;
                pC += w.x*xc.x + w.y*xc.y + w.z*xc.z + w.w*xc.w;
                pD += w.x*xd.x + w.y*xd.y + w.z*xd.z + w.w*xd.w;
            }
            gsig[(ndD     ) * 16 + go] = 1.0f / (1.0f + __expf(-(pA + bg)));
            gsig[(ndD + 16) * 16 + go] = 1.0f / (1.0f + __expf(-(pB + bg)));
            gsig[(ndD + 32) * 16 + go] = 1.0f / (1.0f + __expf(-(pC + bg)));
            gsig[(ndD + 48) * 16 + go] = 1.0f / (1.0f + __expf(-(pD + bg)));
        }
#pragma unroll
        for (int r = 0; r < 8; r++) {
            int nd = wid + 8 * r;
            int node = nb + nd;
            float4 v = *reinterpret_cast<const float4*>(ssm + nd * 132 + lane * 4);
            if (node < n_nodes)
                reinterpret_cast<float4*>(out_s + (size_t)node * 128)[lane] = v;
        }
        __syncthreads();

        // ===== Phase E: gated vector output =====
#pragma unroll
        for (int r = 0; r < 12; r++) {
            int i = t + 256 * r;
            int nd = i / 48, j = i - nd * 48;
            int o = j / 3, x = j - o * 3;
            float a = 0.f;
#pragma unroll
            for (int h = 0; h < 16; h++)
                a += vh[nd * 50 + x * 16 + h] * sWup[o * 16 + h];
            int node = nb + nd;
            if (node < n_nodes)
                out_v[(size_t)node * 48 + j] = a * gsig[nd * 16 + o];
        }
        __syncthreads();
    }
}

extern "C" void kernel_launch(void* const* d_in, const int* in_sizes, int n_in,
                              void* d_out, int out_size) {
    const float* scalar = (const float*)d_in[0];
    const float* vector = (const float*)d_in[1];
    const int*   ei     = (const int*)d_in[2];
    const float* frames = (const float*)d_in[3];
    const float* W_down = (const float*)d_in[4];
    const float* W_df   = (const float*)d_in[5];
    const float* W_so   = (const float*)d_in[6];
    const float* b_so   = (const float*)d_in[7];
    const float* W_up   = (const float*)d_in[8];
    const float* W_g    = (const float*)d_in[9];
    const float* b_g    = (const float*)d_in[10];

    int n = in_sizes[0] / S_IN;
    int e = in_sizes[2] / 2;

    float* out_s = (float*)d_out;
    float* out_v = out_s + (size_t)n * S_OUT;

    size_t pre_jobs = (size_t)NREP * n * 4;
    if (pre_jobs < (size_t)n) pre_jobs = n;
    if (pre_jobs < (size_t)K_MERGED * 128) pre_jobs = K_MERGED * 128;

    cudaFuncSetAttribute(k_post, cudaFuncAttributeMaxDynamicSharedMemorySize,
                         SMEM_BYTES);

    k_pre<<<(int)((pre_jobs + 255) / 256), 256>>>(vector, W_df, W_so, W_g, n);
    k_edge<<<(e + 255) / 256, 256>>>(ei, frames, e, n);
    k_fold<<<(n + 255) / 256, 256>>>(n);
    k_post<<<444, 256, SMEM_BYTES>>>(scalar, vector, W_down, b_so, W_up, b_g,
                                     out_s, out_v, n);
}

// round 13
// speedup vs baseline: 1.1867x; 1.1867x over previous
#include <cuda_runtime.h>
#include <math.h>

#define NN_MAX 50000
#define S_IN 128
#define S_OUT 128
#define K_MERGED 153
#define EPSS 1e-8f
#define NREP 8
#define TILE 32
#define MROW 36    // mT2 row (32 nodes + 4 pad), 144B = 16B-aligned
#define ASTRIDE 12 // g_acc per-(rep,node) floats: 9 sums + cnt + 2 pad, 48B

// Scratch (static device globals)
__device__ float g_vdf[NN_MAX * 12];
__device__ float g_acc[(size_t)NREP * NN_MAX * ASTRIDE];
__device__ float g_WsoT[K_MERGED * 128];   // [k][col]
__device__ float g_WgT[128 * 16];          // blocked: [k4][o][kk], k=k4*4+kk
__device__ unsigned int g_ticket;          // dynamic tile counter (zeroed in k_pre)

// ---------------------------------------------------------------------------
// K1: zero accumulators + ticket, compute vdf, transpose W_so and W_g
// ---------------------------------------------------------------------------
__global__ void k_pre(const float* __restrict__ vector,
                      const float* __restrict__ W_df,
                      const float* __restrict__ W_so,
                      const float* __restrict__ W_g,
                      int n_nodes)
{
    int tid = blockIdx.x * blockDim.x + threadIdx.x;

    if (tid == 0) g_ticket = 0u;

    size_t nzero4 = (size_t)NREP * n_nodes * (ASTRIDE / 4);
    if ((size_t)tid < nzero4)
        reinterpret_cast<float4*>(g_acc)[tid] = make_float4(0.f, 0.f, 0.f, 0.f);

    if (tid < K_MERGED * 128) {
        int k = tid >> 7, o = tid & 127;
        g_WsoT[tid] = W_so[o * K_MERGED + k];
    }
    if (tid < 2048) {
        int kk = tid & 3, o = (tid >> 2) & 15, k4 = tid >> 6;
        g_WgT[tid] = W_g[o * 128 + k4 * 4 + kk];
    }

    if (tid >= n_nodes) return;
    int n = tid;

    float v[48];
    const float4* vp = reinterpret_cast<const float4*>(vector + (size_t)n * 48);
#pragma unroll
    for (int q = 0; q < 12; q++) {
        float4 f = vp[q];
        v[q*4+0] = f.x; v[q*4+1] = f.y; v[q*4+2] = f.z; v[q*4+3] = f.w;
    }
#pragma unroll
    for (int j = 0; j < 3; j++) {
        float r0 = 0.f, r1 = 0.f, r2 = 0.f;
#pragma unroll
        for (int i = 0; i < 16; i++) {
            float x = v[i*3 + j];
            r0 += x * __ldg(&W_df[i]);
            r1 += x * __ldg(&W_df[16 + i]);
            r2 += x * __ldg(&W_df[32 + i]);
        }
        g_vdf[(size_t)n*12 + j*3 + 0] = r0;
        g_vdf[(size_t)n*12 + j*3 + 1] = r1;
        g_vdf[(size_t)n*12 + j*3 + 2] = r2;
    }
}

// ---------------------------------------------------------------------------
// K2: per-edge rotation + replicated scatter-add (replica = e & 7)
// ---------------------------------------------------------------------------
__global__ void k_edge(const int* __restrict__ ei,
                       const float* __restrict__ frames,
                       int n_edges, int n_nodes)
{
    int e = blockIdx.x * blockDim.x + threadIdx.x;
    if (e >= n_edges) return;

    int row = ei[e];

    const float4* vp = reinterpret_cast<const float4*>(g_vdf + (size_t)row * 12);
    float4 va = vp[0], vb = vp[1], vc = vp[2];
    float v[9] = { va.x, va.y, va.z, va.w, vb.x, vb.y, vb.z, vb.w, vc.x };

    const float* f = frames + (size_t)e * 9;
    float F[9];
#pragma unroll
    for (int i = 0; i < 9; i++) F[i] = __ldg(&f[i]);

    float loc[9];
#pragma unroll
    for (int x = 0; x < 3; x++)
#pragma unroll
        for (int c = 0; c < 3; c++)
            loc[c*3 + x] = F[x*3+0]*v[0+c] + F[x*3+1]*v[3+c] + F[x*3+2]*v[6+c];

    int rep = e & (NREP - 1);
    float* dst = g_acc + ((size_t)rep * n_nodes + row) * ASTRIDE;
    asm volatile("red.global.add.v4.f32 [%0], {%1,%2,%3,%4};" ::
                 "l"(dst), "f"(loc[0]), "f"(loc[1]), "f"(loc[2]), "f"(loc[3]) : "memory");
    asm volatile("red.global.add.v4.f32 [%0], {%1,%2,%3,%4};" ::
                 "l"(dst+4), "f"(loc[4]), "f"(loc[5]), "f"(loc[6]), "f"(loc[7]) : "memory");
    asm volatile("red.global.add.v2.f32 [%0], {%1,%2};" ::
                 "l"(dst+8), "f"(loc[8]), "f"(1.0f) : "memory");
}

// ---------------------------------------------------------------------------
// K3: node MLP. 32-node tiles; warp = 64 cols x 8 nodes (2 cols/lane):
// weight LDG.64, merged via 16B LDS broadcasts, 2 MOV dup, 8 FFMA2/k.
// Dynamic ticket-based tile scheduling. Replica fold fused into phase A.
// ---------------------------------------------------------------------------
__global__ __launch_bounds__(256, 4) void k_post(
    const float* __restrict__ scalar, const float* __restrict__ vector,
    const float* __restrict__ W_down, const float* __restrict__ b_so,
    const float* __restrict__ W_up,
    const float* __restrict__ b_g,
    float* __restrict__ out_s, float* __restrict__ out_v, int n_nodes)
{
    const int t = threadIdx.x;
    const int lane = t & 31;
    const int wid = t >> 5;

    // GEMM assignment: 2 cols, 8 nodes
    const int colh = wid & 1;
    const int nd0g = (wid >> 1) * 8;
    const int c0 = colh * 64 + lane * 2;

    const float2 bso2 = *reinterpret_cast<const float2*>(b_so + c0);

    // gates: o = t&15; nodes ndA = t>>4 and ndA+16
    const int go = t & 15;
    const int ndA = t >> 4;
    const float bg = b_g[go];

    __shared__ __align__(16) float mT2[K_MERGED * MROW];  // k-major merged
    __shared__ __align__(16) float uni[TILE * 132];       // ssm (pad 132) ∪ vecs
    __shared__ float vh[TILE * 50];
    __shared__ float gsig[TILE * 16];
    __shared__ float sWdown[256], sWup[256];
    __shared__ int s_tile;

    float* const ssm  = uni;   // [nd*132 + col]
    float* const vecs = uni;   // [nd*52 + c]

    sWdown[t] = W_down[t];
    sWup[t]   = W_up[t];
    __syncthreads();

    const int ntiles = (n_nodes + TILE - 1) / TILE;
    const int acol = t >> 1, ahalf = t & 1;    // phase A mapping

    while (true) {
        if (t == 0) s_tile = (int)atomicAdd(&g_ticket, 1u);
        __syncthreads();
        const int tile = s_tile;
        if (tile >= ntiles) break;
        const int nb = tile * TILE;

        // ===== Phase A: scalar -> mT2 rows, vecs, fused replica fold =====
#pragma unroll 4
        for (int i = 0; i < 16; i++) {
            int nd = ahalf * 16 + i;
            int node = nb + nd;
            float p = (node < n_nodes) ? scalar[(size_t)node * 128 + acol] : 0.f;
            mT2[acol * MROW + nd] = p;
        }
#pragma unroll
        for (int r = 0; r < 2; r++) {
            int idx = t + 256 * r;
            if (idx < 384) {
                int nd = idx / 12, q = idx - nd * 12;
                int node = nb + nd;
                float4 f = (node < n_nodes)
                    ? reinterpret_cast<const float4*>(vector)[(size_t)node * 12 + q]
                    : make_float4(0.f, 0.f, 0.f, 0.f);
                *reinterpret_cast<float4*>(vecs + nd * 52 + q * 4) = f;
            }
        }
        if (t < 32) {
            int nd = t, node = nb + nd;
            float sum[9] = {0,0,0,0,0,0,0,0,0};
            float cnt = 0.f;
            if (node < n_nodes) {
#pragma unroll 2
                for (int r = 0; r < NREP; r++) {
                    const float4* a = reinterpret_cast<const float4*>(
                        g_acc + ((size_t)r * n_nodes + node) * ASTRIDE);
                    float4 p0 = a[0];
                    float4 p1 = a[1];
                    float4 p2 = a[2];
                    sum[0] += p0.x; sum[1] += p0.y; sum[2] += p0.z; sum[3] += p0.w;
                    sum[4] += p1.x; sum[5] += p1.y; sum[6] += p1.z; sum[7] += p1.w;
                    sum[8] += p2.x; cnt += p2.y;
                }
            }
            float inv = 1.0f / fmaxf(cnt, 1.0f);
#pragma unroll
            for (int c = 0; c < 9; c++)
                mT2[(144 + c) * MROW + nd] = sum[c] * inv;
        }
        __syncthreads();

        // ===== Phase B: vh + vnorm rows =====
        {
            int nd = t >> 3, h2 = (t & 7) * 2;
#pragma unroll
            for (int hh = 0; hh < 2; hh++) {
                int h = h2 + hh;
                float a0 = 0.f, a1 = 0.f, a2 = 0.f;
#pragma unroll
                for (int i = 0; i < 16; i++) {
                    float wd = sWdown[h * 16 + i];
                    a0 += vecs[nd * 52 + i * 3 + 0] * wd;
                    a1 += vecs[nd * 52 + i * 3 + 1] * wd;
                    a2 += vecs[nd * 52 + i * 3 + 2] * wd;
                }
                vh[nd * 50 +  0 + h] = a0;
                vh[nd * 50 + 16 + h] = a1;
                vh[nd * 50 + 32 + h] = a2;
                mT2[(128 + h) * MROW + nd] = sqrtf(a0*a0 + a1*a1 + a2*a2 + EPSS);
            }
        }
        __syncthreads();

        // ===== Phase C: outer-product GEMM (2 cols x 8 nodes per lane) =====
        {
            unsigned long long a00=0ULL,a01=0ULL,a02=0ULL,a03=0ULL,
                               a10=0ULL,a11=0ULL,a12=0ULL,a13=0ULL;
            const float* wbase = g_WsoT + c0;
            const float* mbase = mT2 + nd0g;
#pragma unroll 3
            for (int k = 0; k < K_MERGED; k++) {
                float2 w = __ldg(reinterpret_cast<const float2*>(wbase + (size_t)k * 128));
                ulonglong2 mA = *reinterpret_cast<const ulonglong2*>(mbase + (size_t)k * MROW);
                ulonglong2 mB = *reinterpret_cast<const ulonglong2*>(mbase + (size_t)k * MROW + 4);
                unsigned long long wd0, wd1;
                asm("mov.b64 %0, {%1, %1};" : "=l"(wd0) : "f"(w.x));
                asm("mov.b64 %0, {%1, %1};" : "=l"(wd1) : "f"(w.y));
                asm("fma.rn.f32x2 %0, %1, %2, %0;" : "+l"(a00) : "l"(wd0), "l"(mA.x));
                asm("fma.rn.f32x2 %0, %1, %2, %0;" : "+l"(a01) : "l"(wd0), "l"(mA.y));
                asm("fma.rn.f32x2 %0, %1, %2, %0;" : "+l"(a02) : "l"(wd0), "l"(mB.x));
                asm("fma.rn.f32x2 %0, %1, %2, %0;" : "+l"(a03) : "l"(wd0), "l"(mB.y));
                asm("fma.rn.f32x2 %0, %1, %2, %0;" : "+l"(a10) : "l"(wd1), "l"(mA.x));
                asm("fma.rn.f32x2 %0, %1, %2, %0;" : "+l"(a11) : "l"(wd1), "l"(mA.y));
                asm("fma.rn.f32x2 %0, %1, %2, %0;" : "+l"(a12) : "l"(wd1), "l"(mB.x));
                asm("fma.rn.f32x2 %0, %1, %2, %0;" : "+l"(a13) : "l"(wd1), "l"(mB.y));
            }
            // epilogue: acc halves = nodes (nd0g+2p, nd0g+2p+1), cols c0,c0+1
            unsigned long long acc0[4] = {a00,a01,a02,a03};
            unsigned long long acc1[4] = {a10,a11,a12,a13};
#pragma unroll
            for (int p = 0; p < 4; p++) {
                float lo0, hi0, lo1, hi1;
                asm("mov.b64 {%0, %1}, %2;" : "=f"(lo0), "=f"(hi0) : "l"(acc0[p]));
                asm("mov.b64 {%0, %1}, %2;" : "=f"(lo1), "=f"(hi1) : "l"(acc1[p]));
                float sv00 = lo0 + bso2.x, sv01 = lo1 + bso2.y;
                float sv10 = hi0 + bso2.x, sv11 = hi1 + bso2.y;
                float s00 = sv00 / (1.0f + __expf(-sv00));
                float s01 = sv01 / (1.0f + __expf(-sv01));
                float s10 = sv10 / (1.0f + __expf(-sv10));
                float s11 = sv11 / (1.0f + __expf(-sv11));
                *reinterpret_cast<float2*>(ssm + (nd0g + 2*p    ) * 132 + c0) =
                    make_float2(s00, s01);
                *reinterpret_cast<float2*>(ssm + (nd0g + 2*p + 1) * 132 + c0) =
                    make_float2(s10, s11);
            }
        }
        __syncthreads();

        // ===== Phase D: gates (blocked transposed weights) + out_s =====
        {
            float pA = 0.f, pB = 0.f;
            const float4* wgt = reinterpret_cast<const float4*>(g_WgT + go * 4);
            const float4* sA4 = reinterpret_cast<const float4*>(ssm + ndA * 132);
            const float4* sB4 = reinterpret_cast<const float4*>(ssm + (ndA + 16) * 132);
#pragma unroll 8
            for (int k4 = 0; k4 < 32; k4++) {
                float4 w = __ldg(wgt + k4 * 16);
                float4 xa = sA4[k4];
                float4 xb = sB4[k4];
                pA += w.x*xa.x + w.y*xa.y + w.z*xa.z + w.w*xa.w;
                pB += w.x*xb.x + w.y*xb.y + w.z*xb.z + w.w*xb.w;
            }
            gsig[ndA * 16 + go]        = 1.0f / (1.0f + __expf(-(pA + bg)));
            gsig[(ndA + 16) * 16 + go] = 1.0f / (1.0f + __expf(-(pB + bg)));
        }
#pragma unroll
        for (int r = 0; r < 4; r++) {
            int nd = wid + 8 * r;
            int node = nb + nd;
            float4 v = *reinterpret_cast<const float4*>(ssm + nd * 132 + lane * 4);
            if (node < n_nodes)
                reinterpret_cast<float4*>(out_s + (size_t)node * 128)[lane] = v;
        }
        __syncthreads();

        // ===== Phase E: gated vector output =====
#pragma unroll
        for (int r = 0; r < 6; r++) {
            int i = t + 256 * r;
            int nd = i / 48, j = i - nd * 48;
            int o = j / 3, x = j - o * 3;
            float a = 0.f;
#pragma unroll
            for (int h = 0; h < 16; h++)
                a += vh[nd * 50 + x * 16 + h] * sWup[o * 16 + h];
            int node = nb + nd;
            if (node < n_nodes)
                out_v[(size_t)node * 48 + j] = a * gsig[nd * 16 + o];
        }
        __syncthreads();
    }
}

extern "C" void kernel_launch(void* const* d_in, const int* in_sizes, int n_in,
                              void* d_out, int out_size) {
    const float* scalar = (const float*)d_in[0];
    const float* vector = (const float*)d_in[1];
    const int*   ei     = (const int*)d_in[2];
    const float* frames = (const float*)d_in[3];
    const float* W_down = (const float*)d_in[4];
    const float* W_df   = (const float*)d_in[5];
    const float* W_so   = (const float*)d_in[6];
    const float* b_so   = (const float*)d_in[7];
    const float* W_up   = (const float*)d_in[8];
    const float* W_g    = (const float*)d_in[9];
    const float* b_g    = (const float*)d_in[10];

    int n = in_sizes[0] / S_IN;
    int e = in_sizes[2] / 2;

    float* out_s = (float*)d_out;
    float* out_v = out_s + (size_t)n * S_OUT;

    size_t pre_jobs = (size_t)NREP * n * (ASTRIDE / 4);   // zero float4 count
    if (pre_jobs < (size_t)n) pre_jobs = n;
    if (pre_jobs < (size_t)K_MERGED * 128) pre_jobs = K_MERGED * 128;

    k_pre<<<(int)((pre_jobs + 255) / 256), 256>>>(vector, W_df, W_so, W_g, n);
    k_edge<<<(e + 255) / 256, 256>>>(ei, frames, e, n);
    k_post<<<592, 256>>>(scalar, vector, W_down, b_so, W_up, b_g,
                         out_s, out_v, n);
}

// round 14
// speedup vs baseline: 1.2324x; 1.0384x over previous
#include <cuda_runtime.h>
#include <math.h>

#define NN_MAX 50000
#define S_IN 128
#define S_OUT 128
#define K_MERGED 153
#define EPSS 1e-8f
#define NREP 8
#define TILE 32
#define MROW 36    // mT2 row (32 nodes + 4 pad), 144B = 16B-aligned
#define ASTRIDE 12 // g_acc per-(rep,node): 9 frame-sums + cnt + 2 pad, 48B

// Scratch (static device globals)
__device__ float g_acc[(size_t)NREP * NN_MAX * ASTRIDE];
__device__ float g_WsoT[K_MERGED * 128];   // [k][col]
__device__ float g_WgT[128 * 16];          // blocked: [k4][o][kk], k=k4*4+kk
__device__ unsigned int g_ticket;          // dynamic tile counter (zeroed in k_pre)

// ---------------------------------------------------------------------------
// K1: zero accumulators + ticket, transpose W_so and W_g (no vdf anymore)
// ---------------------------------------------------------------------------
__global__ void k_pre(const float* __restrict__ W_so,
                      const float* __restrict__ W_g,
                      int n_nodes)
{
    int tid = blockIdx.x * blockDim.x + threadIdx.x;

    if (tid == 0) g_ticket = 0u;

    size_t nzero4 = (size_t)NREP * n_nodes * (ASTRIDE / 4);
    if ((size_t)tid < nzero4)
        reinterpret_cast<float4*>(g_acc)[tid] = make_float4(0.f, 0.f, 0.f, 0.f);

    if (tid < K_MERGED * 128) {
        int k = tid >> 7, o = tid & 127;
        g_WsoT[tid] = W_so[o * K_MERGED + k];
    }
    if (tid < 2048) {
        int kk = tid & 3, o = (tid >> 2) & 15, k4 = tid >> 6;
        g_WgT[tid] = W_g[o * 128 + k4 * 4 + kk];
    }
}

// ---------------------------------------------------------------------------
// K2: per-edge scatter-add of RAW FRAMES (linearity: rotate once per node
// later, not once per edge). replica = e & 7.
// ---------------------------------------------------------------------------
__global__ void k_edge(const int* __restrict__ ei,
                       const float* __restrict__ frames,
                       int n_edges, int n_nodes)
{
    int e = blockIdx.x * blockDim.x + threadIdx.x;
    if (e >= n_edges) return;

    int row = ei[e];

    const float* f = frames + (size_t)e * 9;
    float F[9];
#pragma unroll
    for (int i = 0; i < 9; i++) F[i] = __ldg(&f[i]);

    int rep = e & (NREP - 1);
    float* dst = g_acc + ((size_t)rep * n_nodes + row) * ASTRIDE;
    asm volatile("red.global.add.v4.f32 [%0], {%1,%2,%3,%4};" ::
                 "l"(dst), "f"(F[0]), "f"(F[1]), "f"(F[2]), "f"(F[3]) : "memory");
    asm volatile("red.global.add.v4.f32 [%0], {%1,%2,%3,%4};" ::
                 "l"(dst+4), "f"(F[4]), "f"(F[5]), "f"(F[6]), "f"(F[7]) : "memory");
    asm volatile("red.global.add.v2.f32 [%0], {%1,%2};" ::
                 "l"(dst+8), "f"(F[8]), "f"(1.0f) : "memory");
}

// ---------------------------------------------------------------------------
// K3: node MLP. 32-node tiles; warp = 64 cols x 8 nodes (2 cols/lane).
// Ticket scheduling. Replica fold (mean frame) fused in phase A; the
// meanF·vdf rotation happens in phase B using vecs + W_df.
// ---------------------------------------------------------------------------
__global__ __launch_bounds__(256, 4) void k_post(
    const float* __restrict__ scalar, const float* __restrict__ vector,
    const float* __restrict__ W_down, const float* __restrict__ W_df,
    const float* __restrict__ b_so,
    const float* __restrict__ W_up,
    const float* __restrict__ b_g,
    float* __restrict__ out_s, float* __restrict__ out_v, int n_nodes)
{
    const int t = threadIdx.x;
    const int lane = t & 31;
    const int wid = t >> 5;

    // GEMM assignment: 2 cols, 8 nodes
    const int colh = wid & 1;
    const int nd0g = (wid >> 1) * 8;
    const int c0 = colh * 64 + lane * 2;

    const float2 bso2 = *reinterpret_cast<const float2*>(b_so + c0);

    // gates: o = t&15; nodes ndA = t>>4 and ndA+16
    const int go = t & 15;
    const int ndA = t >> 4;
    const float bg = b_g[go];

    __shared__ __align__(16) float mT2[K_MERGED * MROW];  // k-major merged
    __shared__ __align__(16) float uni[TILE * 132];       // ssm (pad 132) ∪ vecs
    __shared__ float vh[TILE * 50];
    __shared__ float gsig[TILE * 16];
    __shared__ __align__(16) float sFold[TILE * 12];      // meanF per node
    __shared__ float sWdown[256], sWup[256], sWdf[48];
    __shared__ int s_tile;

    float* const ssm  = uni;   // [nd*132 + col]
    float* const vecs = uni;   // [nd*52 + c]

    sWdown[t] = W_down[t];
    sWup[t]   = W_up[t];
    if (t < 48) sWdf[t] = W_df[t];
    __syncthreads();

    const int ntiles = (n_nodes + TILE - 1) / TILE;
    const int acol = t >> 1, ahalf = t & 1;    // phase A mapping

    while (true) {
        if (t == 0) s_tile = (int)atomicAdd(&g_ticket, 1u);
        __syncthreads();
        const int tile = s_tile;
        if (tile >= ntiles) break;
        const int nb = tile * TILE;

        // ===== Phase A: scalar -> mT2 rows, vecs, replica fold (meanF) =====
#pragma unroll 4
        for (int i = 0; i < 16; i++) {
            int nd = ahalf * 16 + i;
            int node = nb + nd;
            float p = (node < n_nodes) ? scalar[(size_t)node * 128 + acol] : 0.f;
            mT2[acol * MROW + nd] = p;
        }
#pragma unroll
        for (int r = 0; r < 2; r++) {
            int idx = t + 256 * r;
            if (idx < 384) {
                int nd = idx / 12, q = idx - nd * 12;
                int node = nb + nd;
                float4 f = (node < n_nodes)
                    ? reinterpret_cast<const float4*>(vector)[(size_t)node * 12 + q]
                    : make_float4(0.f, 0.f, 0.f, 0.f);
                *reinterpret_cast<float4*>(vecs + nd * 52 + q * 4) = f;
            }
        }
        if (t < 32) {
            int nd = t, node = nb + nd;
            float sum[9] = {0,0,0,0,0,0,0,0,0};
            float cnt = 0.f;
            if (node < n_nodes) {
#pragma unroll 2
                for (int r = 0; r < NREP; r++) {
                    const float4* a = reinterpret_cast<const float4*>(
                        g_acc + ((size_t)r * n_nodes + node) * ASTRIDE);
                    float4 p0 = a[0];
                    float4 p1 = a[1];
                    float4 p2 = a[2];
                    sum[0] += p0.x; sum[1] += p0.y; sum[2] += p0.z; sum[3] += p0.w;
                    sum[4] += p1.x; sum[5] += p1.y; sum[6] += p1.z; sum[7] += p1.w;
                    sum[8] += p2.x; cnt += p2.y;
                }
            }
            float inv = 1.0f / fmaxf(cnt, 1.0f);
#pragma unroll
            for (int c = 0; c < 9; c++)
                sFold[nd * 12 + c] = sum[c] * inv;
        }
        __syncthreads();

        // ===== Phase B: vh + vnorm rows; fold threads also rotate meanF·vdf =====
        {
            int nd = t >> 3, h2 = (t & 7) * 2;
#pragma unroll
            for (int hh = 0; hh < 2; hh++) {
                int h = h2 + hh;
                float a0 = 0.f, a1 = 0.f, a2 = 0.f;
#pragma unroll
                for (int i = 0; i < 16; i++) {
                    float wd = sWdown[h * 16 + i];
                    a0 += vecs[nd * 52 + i * 3 + 0] * wd;
                    a1 += vecs[nd * 52 + i * 3 + 1] * wd;
                    a2 += vecs[nd * 52 + i * 3 + 2] * wd;
                }
                vh[nd * 50 +  0 + h] = a0;
                vh[nd * 50 + 16 + h] = a1;
                vh[nd * 50 + 32 + h] = a2;
                mT2[(128 + h) * MROW + nd] = sqrtf(a0*a0 + a1*a1 + a2*a2 + EPSS);
            }
        }
        if (t < 32) {
            int nd = t;
            // vdf[j][c] = sum_i vecs[nd][i*3+j] * W_df[c][i]
            float vdf[3][3];
#pragma unroll
            for (int c = 0; c < 3; c++) {
                float d0 = 0.f, d1 = 0.f, d2 = 0.f;
#pragma unroll
                for (int i = 0; i < 16; i++) {
                    float w = sWdf[c * 16 + i];
                    d0 += vecs[nd * 52 + i * 3 + 0] * w;
                    d1 += vecs[nd * 52 + i * 3 + 1] * w;
                    d2 += vecs[nd * 52 + i * 3 + 2] * w;
                }
                vdf[0][c] = d0; vdf[1][c] = d1; vdf[2][c] = d2;
            }
            // sh[c*3+x] = sum_j meanF[x*3+j] * vdf[j][c]
#pragma unroll
            for (int x = 0; x < 3; x++) {
                float f0 = sFold[nd * 12 + x * 3 + 0];
                float f1 = sFold[nd * 12 + x * 3 + 1];
                float f2 = sFold[nd * 12 + x * 3 + 2];
#pragma unroll
                for (int c = 0; c < 3; c++) {
                    float sh = f0 * vdf[0][c] + f1 * vdf[1][c] + f2 * vdf[2][c];
                    mT2[(144 + c * 3 + x) * MROW + nd] = sh;
                }
            }
        }
        __syncthreads();

        // ===== Phase C: outer-product GEMM (2 cols x 8 nodes per lane) =====
        {
            unsigned long long a00=0ULL,a01=0ULL,a02=0ULL,a03=0ULL,
                               a10=0ULL,a11=0ULL,a12=0ULL,a13=0ULL;
            const float* wbase = g_WsoT + c0;
            const float* mbase = mT2 + nd0g;
#pragma unroll 3
            for (int k = 0; k < K_MERGED; k++) {
                float2 w = __ldg(reinterpret_cast<const float2*>(wbase + (size_t)k * 128));
                ulonglong2 mA = *reinterpret_cast<const ulonglong2*>(mbase + (size_t)k * MROW);
                ulonglong2 mB = *reinterpret_cast<const ulonglong2*>(mbase + (size_t)k * MROW + 4);
                unsigned long long wd0, wd1;
                asm("mov.b64 %0, {%1, %1};" : "=l"(wd0) : "f"(w.x));
                asm("mov.b64 %0, {%1, %1};" : "=l"(wd1) : "f"(w.y));
                asm("fma.rn.f32x2 %0, %1, %2, %0;" : "+l"(a00) : "l"(wd0), "l"(mA.x));
                asm("fma.rn.f32x2 %0, %1, %2, %0;" : "+l"(a01) : "l"(wd0), "l"(mA.y));
                asm("fma.rn.f32x2 %0, %1, %2, %0;" : "+l"(a02) : "l"(wd0), "l"(mB.x));
                asm("fma.rn.f32x2 %0, %1, %2, %0;" : "+l"(a03) : "l"(wd0), "l"(mB.y));
                asm("fma.rn.f32x2 %0, %1, %2, %0;" : "+l"(a10) : "l"(wd1), "l"(mA.x));
                asm("fma.rn.f32x2 %0, %1, %2, %0;" : "+l"(a11) : "l"(wd1), "l"(mA.y));
                asm("fma.rn.f32x2 %0, %1, %2, %0;" : "+l"(a12) : "l"(wd1), "l"(mB.x));
                asm("fma.rn.f32x2 %0, %1, %2, %0;" : "+l"(a13) : "l"(wd1), "l"(mB.y));
            }
            // epilogue: acc halves = nodes (nd0g+2p, nd0g+2p+1), cols c0,c0+1
            unsigned long long acc0[4] = {a00,a01,a02,a03};
            unsigned long long acc1[4] = {a10,a11,a12,a13};
#pragma unroll
            for (int p = 0; p < 4; p++) {
                float lo0, hi0, lo1, hi1;
                asm("mov.b64 {%0, %1}, %2;" : "=f"(lo0), "=f"(hi0) : "l"(acc0[p]));
                asm("mov.b64 {%0, %1}, %2;" : "=f"(lo1), "=f"(hi1) : "l"(acc1[p]));
                float sv00 = lo0 + bso2.x, sv01 = lo1 + bso2.y;
                float sv10 = hi0 + bso2.x, sv11 = hi1 + bso2.y;
                float s00 = sv00 / (1.0f + __expf(-sv00));
                float s01 = sv01 / (1.0f + __expf(-sv01));
                float s10 = sv10 / (1.0f + __expf(-sv10));
                float s11 = sv11 / (1.0f + __expf(-sv11));
                *reinterpret_cast<float2*>(ssm + (nd0g + 2*p    ) * 132 + c0) =
                    make_float2(s00, s01);
                *reinterpret_cast<float2*>(ssm + (nd0g + 2*p + 1) * 132 + c0) =
                    make_float2(s10, s11);
            }
        }
        __syncthreads();

        // ===== Phase D: gates (blocked transposed weights) + out_s =====
        {
            float pA = 0.f, pB = 0.f;
            const float4* wgt = reinterpret_cast<const float4*>(g_WgT + go * 4);
            const float4* sA4 = reinterpret_cast<const float4*>(ssm + ndA * 132);
            const float4* sB4 = reinterpret_cast<const float4*>(ssm + (ndA + 16) * 132);
#pragma unroll 8
            for (int k4 = 0; k4 < 32; k4++) {
                float4 w = __ldg(wgt + k4 * 16);
                float4 xa = sA4[k4];
                float4 xb = sB4[k4];
                pA += w.x*xa.x + w.y*xa.y + w.z*xa.z + w.w*xa.w;
                pB += w.x*xb.x + w.y*xb.y + w.z*xb.z + w.w*xb.w;
            }
            gsig[ndA * 16 + go]        = 1.0f / (1.0f + __expf(-(pA + bg)));
            gsig[(ndA + 16) * 16 + go] = 1.0f / (1.0f + __expf(-(pB + bg)));
        }
#pragma unroll
        for (int r = 0; r < 4; r++) {
            int nd = wid + 8 * r;
            int node = nb + nd;
            float4 v = *reinterpret_cast<const float4*>(ssm + nd * 132 + lane * 4);
            if (node < n_nodes)
                reinterpret_cast<float4*>(out_s + (size_t)node * 128)[lane] = v;
        }
        __syncthreads();

        // ===== Phase E: gated vector output =====
#pragma unroll
        for (int r = 0; r < 6; r++) {
            int i = t + 256 * r;
            int nd = i / 48, j = i - nd * 48;
            int o = j / 3, x = j - o * 3;
            float a = 0.f;
#pragma unroll
            for (int h = 0; h < 16; h++)
                a += vh[nd * 50 + x * 16 + h] * sWup[o * 16 + h];
            int node = nb + nd;
            if (node < n_nodes)
                out_v[(size_t)node * 48 + j] = a * gsig[nd * 16 + o];
        }
        __syncthreads();
    }
}

extern "C" void kernel_launch(void* const* d_in, const int* in_sizes, int n_in,
                              void* d_out, int out_size) {
    const float* scalar = (const float*)d_in[0];
    const float* vector = (const float*)d_in[1];
    const int*   ei     = (const int*)d_in[2];
    const float* frames = (const float*)d_in[3];
    const float* W_down = (const float*)d_in[4];
    const float* W_df   = (const float*)d_in[5];
    const float* W_so   = (const float*)d_in[6];
    const float* b_so   = (const float*)d_in[7];
    const float* W_up   = (const float*)d_in[8];
    const float* W_g    = (const float*)d_in[9];
    const float* b_g    = (const float*)d_in[10];

    int n = in_sizes[0] / S_IN;
    int e = in_sizes[2] / 2;

    float* out_s = (float*)d_out;
    float* out_v = out_s + (size_t)n * S_OUT;

    size_t pre_jobs = (size_t)NREP * n * (ASTRIDE / 4);   // zero float4 count
    if (pre_jobs < (size_t)K_MERGED * 128) pre_jobs = K_MERGED * 128;

    k_pre<<<(int)((pre_jobs + 255) / 256), 256>>>(W_so, W_g, n);
    k_edge<<<(e + 255) / 256, 256>>>(ei, frames, e, n);
    k_post<<<592, 256>>>(scalar, vector, W_down, W_df, b_so, W_up, b_g,
                         out_s, out_v, n);
}

// round 15
// speedup vs baseline: 1.2342x; 1.0015x over previous
#include <cuda_runtime.h>
#include <math.h>

#define NN_MAX 50000
#define S_IN 128
#define S_OUT 128
#define K_MERGED 153
#define EPSS 1e-8f
#define NREP 8
#define TILE 32
#define MROW 36    // mT2 row (32 nodes + 4 pad), 144B = 16B-aligned
#define ASTRIDE 12 // g_acc per-(rep,node): 9 frame-sums + cnt + 2 pad, 48B

// Scratch (static device globals)
__device__ float g_acc[(size_t)NREP * NN_MAX * ASTRIDE];
__device__ float g_WsoT[K_MERGED * 128];   // [k][col]
__device__ float g_WgT[128 * 16];          // blocked: [k4][o][kk], k=k4*4+kk
__device__ unsigned int g_ticket;          // dynamic tile counter (zeroed in k_pre)

// ---------------------------------------------------------------------------
// K1: zero accumulators + ticket, transpose W_so and W_g
// ---------------------------------------------------------------------------
__global__ void k_pre(const float* __restrict__ W_so,
                      const float* __restrict__ W_g,
                      int n_nodes)
{
    int tid = blockIdx.x * blockDim.x + threadIdx.x;

    if (tid == 0) g_ticket = 0u;

    size_t nzero4 = (size_t)NREP * n_nodes * (ASTRIDE / 4);
    if ((size_t)tid < nzero4)
        reinterpret_cast<float4*>(g_acc)[tid] = make_float4(0.f, 0.f, 0.f, 0.f);

    if (tid < K_MERGED * 128) {
        int k = tid >> 7, o = tid & 127;
        g_WsoT[tid] = W_so[o * K_MERGED + k];
    }
    if (tid < 2048) {
        int kk = tid & 3, o = (tid >> 2) & 15, k4 = tid >> 6;
        g_WgT[tid] = W_g[o * 128 + k4 * 4 + kk];
    }
}

// ---------------------------------------------------------------------------
// K2: per-edge scatter-add of RAW FRAMES (rotation hoisted to k_post via
// linearity). replica = e & 7.
// ---------------------------------------------------------------------------
__global__ void k_edge(const int* __restrict__ ei,
                       const float* __restrict__ frames,
                       int n_edges, int n_nodes)
{
    int e = blockIdx.x * blockDim.x + threadIdx.x;
    if (e >= n_edges) return;

    int row = ei[e];

    const float* f = frames + (size_t)e * 9;
    float F[9];
#pragma unroll
    for (int i = 0; i < 9; i++) F[i] = __ldg(&f[i]);

    int rep = e & (NREP - 1);
    float* dst = g_acc + ((size_t)rep * n_nodes + row) * ASTRIDE;
    asm volatile("red.global.add.v4.f32 [%0], {%1,%2,%3,%4};" ::
                 "l"(dst), "f"(F[0]), "f"(F[1]), "f"(F[2]), "f"(F[3]) : "memory");
    asm volatile("red.global.add.v4.f32 [%0], {%1,%2,%3,%4};" ::
                 "l"(dst+4), "f"(F[4]), "f"(F[5]), "f"(F[6]), "f"(F[7]) : "memory");
    asm volatile("red.global.add.v2.f32 [%0], {%1,%2};" ::
                 "l"(dst+8), "f"(F[8]), "f"(1.0f) : "memory");
}

// ---------------------------------------------------------------------------
// K3: node MLP. 32-node tiles; warp = 64 cols x 8 nodes (2 cols/lane).
// Ticket scheduling; mean-frame fold + meanF·vdf rotation fused.
// Phase B: single-pass vecs loads. Phase E: f32x2 via ld.shared.b64.
// ---------------------------------------------------------------------------
__global__ __launch_bounds__(256, 4) void k_post(
    const float* __restrict__ scalar, const float* __restrict__ vector,
    const float* __restrict__ W_down, const float* __restrict__ W_df,
    const float* __restrict__ b_so,
    const float* __restrict__ W_up,
    const float* __restrict__ b_g,
    float* __restrict__ out_s, float* __restrict__ out_v, int n_nodes)
{
    const int t = threadIdx.x;
    const int lane = t & 31;
    const int wid = t >> 5;

    // GEMM assignment: 2 cols, 8 nodes
    const int colh = wid & 1;
    const int nd0g = (wid >> 1) * 8;
    const int c0 = colh * 64 + lane * 2;

    const float2 bso2 = *reinterpret_cast<const float2*>(b_so + c0);

    // gates: o = t&15; nodes ndA = t>>4 and ndA+16
    const int go = t & 15;
    const int ndA = t >> 4;
    const float bg = b_g[go];

    __shared__ __align__(16) float mT2[K_MERGED * MROW];  // k-major merged
    __shared__ __align__(16) float uni[TILE * 132];       // ssm (pad 132) ∪ vecs
    __shared__ __align__(8) float vh[TILE * 50];
    __shared__ float gsig[TILE * 16];
    __shared__ __align__(16) float sFold[TILE * 12];      // meanF per node
    __shared__ __align__(8) float sWdown[256];
    __shared__ __align__(8) float sWup[256];
    __shared__ float sWdf[48];
    __shared__ int s_tile;

    float* const ssm  = uni;   // [nd*132 + col]
    float* const vecs = uni;   // [nd*52 + c]

    sWdown[t] = W_down[t];
    sWup[t]   = W_up[t];
    if (t < 48) sWdf[t] = W_df[t];
    __syncthreads();

    const int ntiles = (n_nodes + TILE - 1) / TILE;
    const int acol = t >> 1, ahalf = t & 1;    // phase A mapping

    while (true) {
        if (t == 0) s_tile = (int)atomicAdd(&g_ticket, 1u);
        __syncthreads();
        const int tile = s_tile;
        if (tile >= ntiles) break;
        const int nb = tile * TILE;

        // ===== Phase A: scalar -> mT2 rows, vecs, replica fold (meanF) =====
#pragma unroll 4
        for (int i = 0; i < 16; i++) {
            int nd = ahalf * 16 + i;
            int node = nb + nd;
            float p = (node < n_nodes) ? scalar[(size_t)node * 128 + acol] : 0.f;
            mT2[acol * MROW + nd] = p;
        }
#pragma unroll
        for (int r = 0; r < 2; r++) {
            int idx = t + 256 * r;
            if (idx < 384) {
                int nd = idx / 12, q = idx - nd * 12;
                int node = nb + nd;
                float4 f = (node < n_nodes)
                    ? reinterpret_cast<const float4*>(vector)[(size_t)node * 12 + q]
                    : make_float4(0.f, 0.f, 0.f, 0.f);
                *reinterpret_cast<float4*>(vecs + nd * 52 + q * 4) = f;
            }
        }
        if (t < 32) {
            int nd = t, node = nb + nd;
            float sum[9] = {0,0,0,0,0,0,0,0,0};
            float cnt = 0.f;
            if (node < n_nodes) {
#pragma unroll 2
                for (int r = 0; r < NREP; r++) {
                    const float4* a = reinterpret_cast<const float4*>(
                        g_acc + ((size_t)r * n_nodes + node) * ASTRIDE);
                    float4 p0 = a[0];
                    float4 p1 = a[1];
                    float4 p2 = a[2];
                    sum[0] += p0.x; sum[1] += p0.y; sum[2] += p0.z; sum[3] += p0.w;
                    sum[4] += p1.x; sum[5] += p1.y; sum[6] += p1.z; sum[7] += p1.w;
                    sum[8] += p2.x; cnt += p2.y;
                }
            }
            float inv = 1.0f / fmaxf(cnt, 1.0f);
#pragma unroll
            for (int c = 0; c < 9; c++)
                sFold[nd * 12 + c] = sum[c] * inv;
        }
        __syncthreads();

        // ===== Phase B: vh + vnorm rows (single-pass vecs loads) =====
        {
            int nd = t >> 3, h2 = (t & 7) * 2;
            float a00 = 0.f, a01 = 0.f, a02 = 0.f;   // h = h2
            float a10 = 0.f, a11 = 0.f, a12 = 0.f;   // h = h2+1
#pragma unroll
            for (int i = 0; i < 16; i++) {
                float v0 = vecs[nd * 52 + i * 3 + 0];
                float v1 = vecs[nd * 52 + i * 3 + 1];
                float v2 = vecs[nd * 52 + i * 3 + 2];
                float w0 = sWdown[h2 * 16 + i];
                float w1 = sWdown[(h2 + 1) * 16 + i];
                a00 += v0 * w0; a01 += v1 * w0; a02 += v2 * w0;
                a10 += v0 * w1; a11 += v1 * w1; a12 += v2 * w1;
            }
            vh[nd * 50 +  0 + h2] = a00;
            vh[nd * 50 + 16 + h2] = a01;
            vh[nd * 50 + 32 + h2] = a02;
            mT2[(128 + h2) * MROW + nd] = sqrtf(a00*a00 + a01*a01 + a02*a02 + EPSS);
            vh[nd * 50 +  0 + h2 + 1] = a10;
            vh[nd * 50 + 16 + h2 + 1] = a11;
            vh[nd * 50 + 32 + h2 + 1] = a12;
            mT2[(128 + h2 + 1) * MROW + nd] = sqrtf(a10*a10 + a11*a11 + a12*a12 + EPSS);
        }
        if (t < 32) {
            int nd = t;
            // vdf[j][c] = sum_i vecs[nd][i*3+j] * W_df[c][i]
            float vdf[3][3];
#pragma unroll
            for (int c = 0; c < 3; c++) {
                float d0 = 0.f, d1 = 0.f, d2 = 0.f;
#pragma unroll
                for (int i = 0; i < 16; i++) {
                    float w = sWdf[c * 16 + i];
                    d0 += vecs[nd * 52 + i * 3 + 0] * w;
                    d1 += vecs[nd * 52 + i * 3 + 1] * w;
                    d2 += vecs[nd * 52 + i * 3 + 2] * w;
                }
                vdf[0][c] = d0; vdf[1][c] = d1; vdf[2][c] = d2;
            }
            // sh[c*3+x] = sum_j meanF[x*3+j] * vdf[j][c]
#pragma unroll
            for (int x = 0; x < 3; x++) {
                float f0 = sFold[nd * 12 + x * 3 + 0];
                float f1 = sFold[nd * 12 + x * 3 + 1];
                float f2 = sFold[nd * 12 + x * 3 + 2];
#pragma unroll
                for (int c = 0; c < 3; c++) {
                    float sh = f0 * vdf[0][c] + f1 * vdf[1][c] + f2 * vdf[2][c];
                    mT2[(144 + c * 3 + x) * MROW + nd] = sh;
                }
            }
        }
        __syncthreads();

        // ===== Phase C: outer-product GEMM (2 cols x 8 nodes per lane) =====
        {
            unsigned long long a00=0ULL,a01=0ULL,a02=0ULL,a03=0ULL,
                               a10=0ULL,a11=0ULL,a12=0ULL,a13=0ULL;
            const float* wbase = g_WsoT + c0;
            const float* mbase = mT2 + nd0g;
#pragma unroll 3
            for (int k = 0; k < K_MERGED; k++) {
                float2 w = __ldg(reinterpret_cast<const float2*>(wbase + (size_t)k * 128));
                ulonglong2 mA = *reinterpret_cast<const ulonglong2*>(mbase + (size_t)k * MROW);
                ulonglong2 mB = *reinterpret_cast<const ulonglong2*>(mbase + (size_t)k * MROW + 4);
                unsigned long long wd0, wd1;
                asm("mov.b64 %0, {%1, %1};" : "=l"(wd0) : "f"(w.x));
                asm("mov.b64 %0, {%1, %1};" : "=l"(wd1) : "f"(w.y));
                asm("fma.rn.f32x2 %0, %1, %2, %0;" : "+l"(a00) : "l"(wd0), "l"(mA.x));
                asm("fma.rn.f32x2 %0, %1, %2, %0;" : "+l"(a01) : "l"(wd0), "l"(mA.y));
                asm("fma.rn.f32x2 %0, %1, %2, %0;" : "+l"(a02) : "l"(wd0), "l"(mB.x));
                asm("fma.rn.f32x2 %0, %1, %2, %0;" : "+l"(a03) : "l"(wd0), "l"(mB.y));
                asm("fma.rn.f32x2 %0, %1, %2, %0;" : "+l"(a10) : "l"(wd1), "l"(mA.x));
                asm("fma.rn.f32x2 %0, %1, %2, %0;" : "+l"(a11) : "l"(wd1), "l"(mA.y));
                asm("fma.rn.f32x2 %0, %1, %2, %0;" : "+l"(a12) : "l"(wd1), "l"(mB.x));
                asm("fma.rn.f32x2 %0, %1, %2, %0;" : "+l"(a13) : "l"(wd1), "l"(mB.y));
            }
            unsigned long long acc0[4] = {a00,a01,a02,a03};
            unsigned long long acc1[4] = {a10,a11,a12,a13};
#pragma unroll
            for (int p = 0; p < 4; p++) {
                float lo0, hi0, lo1, hi1;
                asm("mov.b64 {%0, %1}, %2;" : "=f"(lo0), "=f"(hi0) : "l"(acc0[p]));
                asm("mov.b64 {%0, %1}, %2;" : "=f"(lo1), "=f"(hi1) : "l"(acc1[p]));
                float sv00 = lo0 + bso2.x, sv01 = lo1 + bso2.y;
                float sv10 = hi0 + bso2.x, sv11 = hi1 + bso2.y;
                float s00 = sv00 / (1.0f + __expf(-sv00));
                float s01 = sv01 / (1.0f + __expf(-sv01));
                float s10 = sv10 / (1.0f + __expf(-sv10));
                float s11 = sv11 / (1.0f + __expf(-sv11));
                *reinterpret_cast<float2*>(ssm + (nd0g + 2*p    ) * 132 + c0) =
                    make_float2(s00, s01);
                *reinterpret_cast<float2*>(ssm + (nd0g + 2*p + 1) * 132 + c0) =
                    make_float2(s10, s11);
            }
        }
        __syncthreads();

        // ===== Phase D: gates (blocked transposed weights) + out_s =====
        {
            float pA = 0.f, pB = 0.f;
            const float4* wgt = reinterpret_cast<const float4*>(g_WgT + go * 4);
            const float4* sA4 = reinterpret_cast<const float4*>(ssm + ndA * 132);
            const float4* sB4 = reinterpret_cast<const float4*>(ssm + (ndA + 16) * 132);
#pragma unroll 8
            for (int k4 = 0; k4 < 32; k4++) {
                float4 w = __ldg(wgt + k4 * 16);
                float4 xa = sA4[k4];
                float4 xb = sB4[k4];
                pA += w.x*xa.x + w.y*xa.y + w.z*xa.z + w.w*xa.w;
                pB += w.x*xb.x + w.y*xb.y + w.z*xb.z + w.w*xb.w;
            }
            gsig[ndA * 16 + go]        = 1.0f / (1.0f + __expf(-(pA + bg)));
            gsig[(ndA + 16) * 16 + go] = 1.0f / (1.0f + __expf(-(pB + bg)));
        }
#pragma unroll
        for (int r = 0; r < 4; r++) {
            int nd = wid + 8 * r;
            int node = nb + nd;
            float4 v = *reinterpret_cast<const float4*>(ssm + nd * 132 + lane * 4);
            if (node < n_nodes)
                reinterpret_cast<float4*>(out_s + (size_t)node * 128)[lane] = v;
        }
        __syncthreads();

        // ===== Phase E: gated vector output (f32x2 over h-pairs) =====
#pragma unroll
        for (int r = 0; r < 6; r++) {
            int i = t + 256 * r;
            int nd = i / 48, j = i - nd * 48;
            int o = j / 3, x = j - o * 3;
            const unsigned long long* vh2 =
                reinterpret_cast<const unsigned long long*>(vh + nd * 50 + x * 16);
            const unsigned long long* wu2 =
                reinterpret_cast<const unsigned long long*>(sWup + o * 16);
            unsigned long long acc = 0ULL;
#pragma unroll
            for (int q = 0; q < 8; q++) {
                asm("fma.rn.f32x2 %0, %1, %2, %0;" : "+l"(acc) : "l"(vh2[q]), "l"(wu2[q]));
            }
            float lo, hi;
            asm("mov.b64 {%0, %1}, %2;" : "=f"(lo), "=f"(hi) : "l"(acc));
            float a = lo + hi;
            int node = nb + nd;
            if (node < n_nodes)
                out_v[(size_t)node * 48 + j] = a * gsig[nd * 16 + o];
        }
        __syncthreads();
    }
}

extern "C" void kernel_launch(void* const* d_in, const int* in_sizes, int n_in,
                              void* d_out, int out_size) {
    const float* scalar = (const float*)d_in[0];
    const float* vector = (const float*)d_in[1];
    const int*   ei     = (const int*)d_in[2];
    const float* frames = (const float*)d_in[3];
    const float* W_down = (const float*)d_in[4];
    const float* W_df   = (const float*)d_in[5];
    const float* W_so   = (const float*)d_in[6];
    const float* b_so   = (const float*)d_in[7];
    const float* W_up   = (const float*)d_in[8];
    const float* W_g    = (const float*)d_in[9];
    const float* b_g    = (const float*)d_in[10];

    int n = in_sizes[0] / S_IN;
    int e = in_sizes[2] / 2;

    float* out_s = (float*)d_out;
    float* out_v = out_s + (size_t)n * S_OUT;

    size_t pre_jobs = (size_t)NREP * n * (ASTRIDE / 4);   // zero float4 count
    if (pre_jobs < (size_t)K_MERGED * 128) pre_jobs = K_MERGED * 128;

    k_pre<<<(int)((pre_jobs + 255) / 256), 256>>>(W_so, W_g, n);
    k_edge<<<(e + 255) / 256, 256>>>(ei, frames, e, n);
    k_post<<<592, 256>>>(scalar, vector, W_down, W_df, b_so, W_up, b_g,
                         out_s, out_v, n);
}

// round 17
// speedup vs baseline: 1.2373x; 1.0025x over previous
#include <cuda_runtime.h>
#include <math.h>

#define NN_MAX 50000
#define S_IN 128
#define S_OUT 128
#define K_MERGED 153
#define EPSS 1e-8f
#define NREP 8
#define TILE 32
#define MROW 36    // mT2 row (32 nodes + 4 pad), 144B = 16B-aligned
#define ASTRIDE 12 // g_acc per-(rep,node): 9 frame-sums + cnt + 2 pad, 48B

// Scratch (static device globals)
__device__ float g_acc[(size_t)NREP * NN_MAX * ASTRIDE];
__device__ float g_WsoT[K_MERGED * 128];   // [k][col]
__device__ float g_WgT[128 * 16];          // blocked: [k4][o][kk], k=k4*4+kk
__device__ unsigned int g_ticket;          // dynamic tile counter (zeroed in k_pre)

// ---------------------------------------------------------------------------
// K1: zero accumulators + ticket, transpose W_so and W_g
// ---------------------------------------------------------------------------
__global__ void k_pre(const float* __restrict__ W_so,
                      const float* __restrict__ W_g,
                      int n_nodes)
{
    int tid = blockIdx.x * blockDim.x + threadIdx.x;

    if (tid == 0) g_ticket = 0u;

    size_t nzero4 = (size_t)NREP * n_nodes * (ASTRIDE / 4);
    if ((size_t)tid < nzero4)
        reinterpret_cast<float4*>(g_acc)[tid] = make_float4(0.f, 0.f, 0.f, 0.f);

    if (tid < K_MERGED * 128) {
        int k = tid >> 7, o = tid & 127;
        g_WsoT[tid] = W_so[o * K_MERGED + k];
    }
    if (tid < 2048) {
        int kk = tid & 3, o = (tid >> 2) & 15, k4 = tid >> 6;
        g_WgT[tid] = W_g[o * 128 + k4 * 4 + kk];
    }
}

// ---------------------------------------------------------------------------
// K2: per-edge scatter-add of RAW FRAMES (rotation hoisted to k_post via
// linearity). replica = e & 7.
// ---------------------------------------------------------------------------
__global__ void k_edge(const int* __restrict__ ei,
                       const float* __restrict__ frames,
                       int n_edges, int n_nodes)
{
    int e = blockIdx.x * blockDim.x + threadIdx.x;
    if (e >= n_edges) return;

    int row = ei[e];

    const float* f = frames + (size_t)e * 9;
    float F[9];
#pragma unroll
    for (int i = 0; i < 9; i++) F[i] = __ldg(&f[i]);

    int rep = e & (NREP - 1);
    float* dst = g_acc + ((size_t)rep * n_nodes + row) * ASTRIDE;
    asm volatile("red.global.add.v4.f32 [%0], {%1,%2,%3,%4};" ::
                 "l"(dst), "f"(F[0]), "f"(F[1]), "f"(F[2]), "f"(F[3]) : "memory");
    asm volatile("red.global.add.v4.f32 [%0], {%1,%2,%3,%4};" ::
                 "l"(dst+4), "f"(F[4]), "f"(F[5]), "f"(F[6]), "f"(F[7]) : "memory");
    asm volatile("red.global.add.v2.f32 [%0], {%1,%2};" ::
                 "l"(dst+8), "f"(F[8]), "f"(1.0f) : "memory");
}

// ---------------------------------------------------------------------------
// K3: node MLP. 32-node tiles; warp = 64 cols x 8 nodes (2 cols/lane).
// Ticket scheduling; mean-frame fold + meanF·vdf rotation fused.
// Phase C: weight LDG software-pipelined one k ahead.
// ---------------------------------------------------------------------------
__global__ __launch_bounds__(256, 4) void k_post(
    const float* __restrict__ scalar, const float* __restrict__ vector,
    const float* __restrict__ W_down, const float* __restrict__ W_df,
    const float* __restrict__ b_so,
    const float* __restrict__ W_up,
    const float* __restrict__ b_g,
    float* __restrict__ out_s, float* __restrict__ out_v, int n_nodes)
{
    const int t = threadIdx.x;
    const int lane = t & 31;
    const int wid = t >> 5;

    // GEMM assignment: 2 cols, 8 nodes
    const int colh = wid & 1;
    const int nd0g = (wid >> 1) * 8;
    const int c0 = colh * 64 + lane * 2;

    const float2 bso2 = *reinterpret_cast<const float2*>(b_so + c0);

    // gates: o = t&15; nodes ndA = t>>4 and ndA+16
    const int go = t & 15;
    const int ndA = t >> 4;
    const float bg = b_g[go];

    __shared__ __align__(16) float mT2[K_MERGED * MROW];  // k-major merged
    __shared__ __align__(16) float uni[TILE * 132];       // ssm (pad 132) ∪ vecs
    __shared__ __align__(8) float vh[TILE * 50];
    __shared__ float gsig[TILE * 16];
    __shared__ __align__(16) float sFold[TILE * 12];      // meanF per node
    __shared__ __align__(8) float sWdown[256];
    __shared__ __align__(8) float sWup[256];
    __shared__ float sWdf[48];
    __shared__ int s_tile;

    float* const ssm  = uni;   // [nd*132 + col]
    float* const vecs = uni;   // [nd*52 + c]

    sWdown[t] = W_down[t];
    sWup[t]   = W_up[t];
    if (t < 48) sWdf[t] = W_df[t];
    __syncthreads();

    const int ntiles = (n_nodes + TILE - 1) / TILE;
    const int acol = t >> 1, ahalf = t & 1;    // phase A mapping

    while (true) {
        if (t == 0) s_tile = (int)atomicAdd(&g_ticket, 1u);
        __syncthreads();
        const int tile = s_tile;
        if (tile >= ntiles) break;
        const int nb = tile * TILE;

        // ===== Phase A: scalar -> mT2 rows, vecs, replica fold (meanF) =====
#pragma unroll 4
        for (int i = 0; i < 16; i++) {
            int nd = ahalf * 16 + i;
            int node = nb + nd;
            float p = (node < n_nodes) ? scalar[(size_t)node * 128 + acol] : 0.f;
            mT2[acol * MROW + nd] = p;
        }
#pragma unroll
        for (int r = 0; r < 2; r++) {
            int idx = t + 256 * r;
            if (idx < 384) {
                int nd = idx / 12, q = idx - nd * 12;
                int node = nb + nd;
                float4 f = (node < n_nodes)
                    ? reinterpret_cast<const float4*>(vector)[(size_t)node * 12 + q]
                    : make_float4(0.f, 0.f, 0.f, 0.f);
                *reinterpret_cast<float4*>(vecs + nd * 52 + q * 4) = f;
            }
        }
        if (t < 32) {
            int nd = t, node = nb + nd;
            float sum[9] = {0,0,0,0,0,0,0,0,0};
            float cnt = 0.f;
            if (node < n_nodes) {
#pragma unroll 2
                for (int r = 0; r < NREP; r++) {
                    const float4* a = reinterpret_cast<const float4*>(
                        g_acc + ((size_t)r * n_nodes + node) * ASTRIDE);
                    float4 p0 = a[0];
                    float4 p1 = a[1];
                    float4 p2 = a[2];
                    sum[0] += p0.x; sum[1] += p0.y; sum[2] += p0.z; sum[3] += p0.w;
                    sum[4] += p1.x; sum[5] += p1.y; sum[6] += p1.z; sum[7] += p1.w;
                    sum[8] += p2.x; cnt += p2.y;
                }
            }
            float inv = 1.0f / fmaxf(cnt, 1.0f);
#pragma unroll
            for (int c = 0; c < 9; c++)
                sFold[nd * 12 + c] = sum[c] * inv;
        }
        __syncthreads();

        // ===== Phase B: vh + vnorm rows (single-pass vecs loads) =====
        {
            int nd = t >> 3, h2 = (t & 7) * 2;
            float a00 = 0.f, a01 = 0.f, a02 = 0.f;   // h = h2
            float a10 = 0.f, a11 = 0.f, a12 = 0.f;   // h = h2+1
#pragma unroll
            for (int i = 0; i < 16; i++) {
                float v0 = vecs[nd * 52 + i * 3 + 0];
                float v1 = vecs[nd * 52 + i * 3 + 1];
                float v2 = vecs[nd * 52 + i * 3 + 2];
                float w0 = sWdown[h2 * 16 + i];
                float w1 = sWdown[(h2 + 1) * 16 + i];
                a00 += v0 * w0; a01 += v1 * w0; a02 += v2 * w0;
                a10 += v0 * w1; a11 += v1 * w1; a12 += v2 * w1;
            }
            vh[nd * 50 +  0 + h2] = a00;
            vh[nd * 50 + 16 + h2] = a01;
            vh[nd * 50 + 32 + h2] = a02;
            mT2[(128 + h2) * MROW + nd] = sqrtf(a00*a00 + a01*a01 + a02*a02 + EPSS);
            vh[nd * 50 +  0 + h2 + 1] = a10;
            vh[nd * 50 + 16 + h2 + 1] = a11;
            vh[nd * 50 + 32 + h2 + 1] = a12;
            mT2[(128 + h2 + 1) * MROW + nd] = sqrtf(a10*a10 + a11*a11 + a12*a12 + EPSS);
        }
        if (t < 32) {
            int nd = t;
            // vdf[j][c] = sum_i vecs[nd][i*3+j] * W_df[c][i]
            float vdf[3][3];
#pragma unroll
            for (int c = 0; c < 3; c++) {
                float d0 = 0.f, d1 = 0.f, d2 = 0.f;
#pragma unroll
                for (int i = 0; i < 16; i++) {
                    float w = sWdf[c * 16 + i];
                    d0 += vecs[nd * 52 + i * 3 + 0] * w;
                    d1 += vecs[nd * 52 + i * 3 + 1] * w;
                    d2 += vecs[nd * 52 + i * 3 + 2] * w;
                }
                vdf[0][c] = d0; vdf[1][c] = d1; vdf[2][c] = d2;
            }
            // sh[c*3+x] = sum_j meanF[x*3+j] * vdf[j][c]
#pragma unroll
            for (int x = 0; x < 3; x++) {
                float f0 = sFold[nd * 12 + x * 3 + 0];
                float f1 = sFold[nd * 12 + x * 3 + 1];
                float f2 = sFold[nd * 12 + x * 3 + 2];
#pragma unroll
                for (int c = 0; c < 3; c++) {
                    float sh = f0 * vdf[0][c] + f1 * vdf[1][c] + f2 * vdf[2][c];
                    mT2[(144 + c * 3 + x) * MROW + nd] = sh;
                }
            }
        }
        __syncthreads();

        // ===== Phase C: GEMM, weight LDG pipelined one k ahead =====
        {
            unsigned long long a00=0ULL,a01=0ULL,a02=0ULL,a03=0ULL,
                               a10=0ULL,a11=0ULL,a12=0ULL,a13=0ULL;
            const float* wbase = g_WsoT + c0;
            const float* mbase = mT2 + nd0g;

            float2 w = __ldg(reinterpret_cast<const float2*>(wbase));
#pragma unroll 3
            for (int k = 0; k < K_MERGED; k++) {
                float2 wn;
                if (k + 1 < K_MERGED)
                    wn = __ldg(reinterpret_cast<const float2*>(wbase + (size_t)(k + 1) * 128));
                ulonglong2 mA = *reinterpret_cast<const ulonglong2*>(mbase + (size_t)k * MROW);
                ulonglong2 mB = *reinterpret_cast<const ulonglong2*>(mbase + (size_t)k * MROW + 4);
                unsigned long long wd0, wd1;
                asm("mov.b64 %0, {%1, %1};" : "=l"(wd0) : "f"(w.x));
                asm("mov.b64 %0, {%1, %1};" : "=l"(wd1) : "f"(w.y));
                asm("fma.rn.f32x2 %0, %1, %2, %0;" : "+l"(a00) : "l"(wd0), "l"(mA.x));
                asm("fma.rn.f32x2 %0, %1, %2, %0;" : "+l"(a01) : "l"(wd0), "l"(mA.y));
                asm("fma.rn.f32x2 %0, %1, %2, %0;" : "+l"(a02) : "l"(wd0), "l"(mB.x));
                asm("fma.rn.f32x2 %0, %1, %2, %0;" : "+l"(a03) : "l"(wd0), "l"(mB.y));
                asm("fma.rn.f32x2 %0, %1, %2, %0;" : "+l"(a10) : "l"(wd1), "l"(mA.x));
                asm("fma.rn.f32x2 %0, %1, %2, %0;" : "+l"(a11) : "l"(wd1), "l"(mA.y));
                asm("fma.rn.f32x2 %0, %1, %2, %0;" : "+l"(a12) : "l"(wd1), "l"(mB.x));
                asm("fma.rn.f32x2 %0, %1, %2, %0;" : "+l"(a13) : "l"(wd1), "l"(mB.y));
                w = wn;
            }
            unsigned long long acc0[4] = {a00,a01,a02,a03};
            unsigned long long acc1[4] = {a10,a11,a12,a13};
#pragma unroll
            for (int p = 0; p < 4; p++) {
                float lo0, hi0, lo1, hi1;
                asm("mov.b64 {%0, %1}, %2;" : "=f"(lo0), "=f"(hi0) : "l"(acc0[p]));
                asm("mov.b64 {%0, %1}, %2;" : "=f"(lo1), "=f"(hi1) : "l"(acc1[p]));
                float sv00 = lo0 + bso2.x, sv01 = lo1 + bso2.y;
                float sv10 = hi0 + bso2.x, sv11 = hi1 + bso2.y;
                float s00 = sv00 / (1.0f + __expf(-sv00));
                float s01 = sv01 / (1.0f + __expf(-sv01));
                float s10 = sv10 / (1.0f + __expf(-sv10));
                float s11 = sv11 / (1.0f + __expf(-sv11));
                *reinterpret_cast<float2*>(ssm + (nd0g + 2*p    ) * 132 + c0) =
                    make_float2(s00, s01);
                *reinterpret_cast<float2*>(ssm + (nd0g + 2*p + 1) * 132 + c0) =
                    make_float2(s10, s11);
            }
        }
        __syncthreads();

        // ===== Phase D: gates (blocked transposed weights) + out_s =====
        {
            float pA = 0.f, pB = 0.f;
            const float4* wgt = reinterpret_cast<const float4*>(g_WgT + go * 4);
            const float4* sA4 = reinterpret_cast<const float4*>(ssm + ndA * 132);
            const float4* sB4 = reinterpret_cast<const float4*>(ssm + (ndA + 16) * 132);
#pragma unroll 8
            for (int k4 = 0; k4 < 32; k4++) {
                float4 w = __ldg(wgt + k4 * 16);
                float4 xa = sA4[k4];
                float4 xb = sB4[k4];
                pA += w.x*xa.x + w.y*xa.y + w.z*xa.z + w.w*xa.w;
                pB += w.x*xb.x + w.y*xb.y + w.z*xb.z + w.w*xb.w;
            }
            gsig[ndA * 16 + go]        = 1.0f / (1.0f + __expf(-(pA + bg)));
            gsig[(ndA + 16) * 16 + go] = 1.0f / (1.0f + __expf(-(pB + bg)));
        }
#pragma unroll
        for (int r = 0; r < 4; r++) {
            int nd = wid + 8 * r;
            int node = nb + nd;
            float4 v = *reinterpret_cast<const float4*>(ssm + nd * 132 + lane * 4);
            if (node < n_nodes)
                reinterpret_cast<float4*>(out_s + (size_t)node * 128)[lane] = v;
        }
        __syncthreads();

        // ===== Phase E: gated vector output (f32x2 over h-pairs) =====
#pragma unroll
        for (int r = 0; r < 6; r++) {
            int i = t + 256 * r;
            int nd = i / 48, j = i - nd * 48;
            int o = j / 3, x = j - o * 3;
            const unsigned long long* vh2 =
                reinterpret_cast<const unsigned long long*>(vh + nd * 50 + x * 16);
            const unsigned long long* wu2 =
                reinterpret_cast<const unsigned long long*>(sWup + o * 16);
            unsigned long long acc = 0ULL;
#pragma unroll
            for (int q = 0; q < 8; q++) {
                asm("fma.rn.f32x2 %0, %1, %2, %0;" : "+l"(acc) : "l"(vh2[q]), "l"(wu2[q]));
            }
            float lo, hi;
            asm("mov.b64 {%0, %1}, %2;" : "=f"(lo), "=f"(hi) : "l"(acc));
            float a = lo + hi;
            int node = nb + nd;
            if (node < n_nodes)
                out_v[(size_t)node * 48 + j] = a * gsig[nd * 16 + o];
        }
        __syncthreads();
    }
}

extern "C" void kernel_launch(void* const* d_in, const int* in_sizes, int n_in,
                              void* d_out, int out_size) {
    const float* scalar = (const float*)d_in[0];
    const float* vector = (const float*)d_in[1];
    const int*   ei     = (const int*)d_in[2];
    const float* frames = (const float*)d_in[3];
    const float* W_down = (const float*)d_in[4];
    const float* W_df   = (const float*)d_in[5];
    const float* W_so   = (const float*)d_in[6];
    const float* b_so   = (const float*)d_in[7];
    const float* W_up   = (const float*)d_in[8];
    const float* W_g    = (const float*)d_in[9];
    const float* b_g    = (const float*)d_in[10];

    int n = in_sizes[0] / S_IN;
    int e = in_sizes[2] / 2;

    float* out_s = (float*)d_out;
    float* out_v = out_s + (size_t)n * S_OUT;

    size_t pre_jobs = (size_t)NREP * n * (ASTRIDE / 4);   // zero float4 count
    if (pre_jobs < (size_t)K_MERGED * 128) pre_jobs = K_MERGED * 128;

    k_pre<<<(int)((pre_jobs + 255) / 256), 256>>>(W_so, W_g, n);
    k_edge<<<(e + 255) / 256, 256>>>(ei, frames, e, n);
    k_post<<<592, 256>>>(scalar, vector, W_down, W_df, b_so, W_up, b_g,
                         out_s, out_v, n);
}